// round 14
// baseline (speedup 1.0000x reference)
#include <cuda_runtime.h>
#include <cuda.h>
#include <cstdint>
#include <cstddef>

#define B_ 256
#define L_ 512
#define D_ 768
#define C_ 19
#define CP 20
#define BL (B_*L_)

// emis staging geometry (TMA): 512 rows/block, stage = 2 boxes of 256 rows
#define KCHUNK 32                           // floats per stage per row (128B)
#define NSTAGE (D_ / KCHUNK)                // 24
#define ROWS_BLK 512
#define BOX_BYTES (256 * 128)               // 32768 (one UTMALDG)
#define STAGE_BYTES (2 * BOX_BYTES)         // 65536 per stage buffer
#define W_BYTES (D_ * 10 * 8)               // 61440 (multiple of 1024)
#define OFF_BUF0 W_BYTES                    // 61440
#define OFF_BUF1 (W_BYTES + STAGE_BYTES)    // 126976
#define OFF_MBAR (W_BYTES + 2 * STAGE_BYTES)// 192512
#define SMEM_TOT (OFF_MBAR + 16)            // 192528

// Emission scratch, padded to 20 floats/row
__device__ float g_emis[(size_t)BL * CP];
// Score history: rows 0..512 per batch
__device__ float g_hist[(size_t)B_ * (L_ + 1) * CP];

__device__ __forceinline__ unsigned long long pack2(float x){
    unsigned long long r;
    asm("mov.b64 %0, {%1, %1};" : "=l"(r) : "f"(x));
    return r;
}
__device__ __forceinline__ unsigned long long fma2(unsigned long long a,
                                                   unsigned long long b,
                                                   unsigned long long c){
    unsigned long long d;
    asm("fma.rn.f32x2 %0, %1, %2, %3;" : "=l"(d) : "l"(a), "l"(b), "l"(c));
    return d;
}
__device__ __forceinline__ uint32_t smem_u32(const void* p){
    uint32_t a;
    asm("{ .reg .u64 t; cvta.to.shared.u64 t, %1; cvt.u32.u64 %0, t; }"
        : "=r"(a) : "l"(p));
    return a;
}
__device__ __forceinline__ void mbar_init(uint32_t mbar, uint32_t cnt){
    asm volatile("mbarrier.init.shared.b64 [%0], %1;" :: "r"(mbar), "r"(cnt) : "memory");
}
__device__ __forceinline__ void mbar_expect_tx(uint32_t mbar, uint32_t bytes){
    asm volatile("mbarrier.arrive.expect_tx.shared.b64 _, [%0], %1;"
                 :: "r"(mbar), "r"(bytes) : "memory");
}
__device__ __forceinline__ void mbar_wait(uint32_t mbar, uint32_t parity){
    asm volatile(
        "{\n\t"
        ".reg .pred P;\n\t"
        "WAIT_%=:\n\t"
        "mbarrier.try_wait.parity.acquire.cta.shared::cta.b64 P, [%0], %1, 0x989680;\n\t"
        "@P bra DONE_%=;\n\t"
        "bra WAIT_%=;\n\t"
        "DONE_%=:\n\t"
        "}" :: "r"(mbar), "r"(parity) : "memory");
}
__device__ __forceinline__ void tma_load_2d(uint32_t smem_addr, const CUtensorMap* tmap,
                                            int cx, int cy, uint32_t mbar){
    asm volatile(
        "cp.async.bulk.tensor.2d.shared::cta.global.tile.mbarrier::complete_tx::bytes "
        "[%0], [%1, {%2, %3}], [%4];"
        :: "r"(smem_addr), "l"(tmap), "r"(cx), "r"(cy), "r"(mbar) : "memory");
}

// ---------------------------------------------------------------------------
// Kernel A: emissions with descriptor TMA staging. 256 blocks x 512 threads,
// 512 rows/block, 1 row/thread: SAME smem/TMA geometry as R13 but 16 warps
// per SM (4/SMSP). R12->R13 showed warps/SMSP is the binding lever
// (4w: 141us, 8w: 119us, both far above the ~63us FMA floor on exposed LDS
// latency). Per-thread work halves; per-SM FMA floor unchanged.
// ---------------------------------------------------------------------------
__global__ void __launch_bounds__(512) emis_kernel(const __grid_constant__ CUtensorMap tmap,
                                                   const float* __restrict__ W,
                                                   const float* __restrict__ bias){
    extern __shared__ char smem_raw[];
    unsigned long long* w2 = reinterpret_cast<unsigned long long*>(smem_raw);
    uint32_t base_u32 = smem_u32(smem_raw);
    uint32_t buf_u32[2] = { base_u32 + OFF_BUF0, base_u32 + OFF_BUF1 };
    uint32_t mbar[2]    = { base_u32 + OFF_MBAR, base_u32 + OFF_MBAR + 8 };
    int tid = threadIdx.x;
    int row_base = blockIdx.x * ROWS_BLK;

    // stage weights: w2[d*10 + p] = (W[2p][d], W[2p+1][d])
    for (int i = tid; i < D_ * 10; i += 512){
        int d = i / 10, p = i % 10;
        float lo = W[(2*p) * D_ + d];
        float hi = (2*p + 1 < C_) ? W[(2*p + 1) * D_ + d] : 0.f;
        float2 t = make_float2(lo, hi);
        w2[i] = *reinterpret_cast<unsigned long long*>(&t);
    }
    if (tid == 0){ mbar_init(mbar[0], 1); mbar_init(mbar[1], 1); }
    __syncthreads();

    if (tid == 0){
        mbar_expect_tx(mbar[0], STAGE_BYTES);
        tma_load_2d(buf_u32[0],             &tmap, 0 * KCHUNK, row_base,       mbar[0]);
        tma_load_2d(buf_u32[0] + BOX_BYTES, &tmap, 0 * KCHUNK, row_base + 256, mbar[0]);
        mbar_expect_tx(mbar[1], STAGE_BYTES);
        tma_load_2d(buf_u32[1],             &tmap, 1 * KCHUNK, row_base,       mbar[1]);
        tma_load_2d(buf_u32[1] + BOX_BYTES, &tmap, 1 * KCHUNK, row_base + 256, mbar[1]);
    }

    unsigned long long acc[10];
#pragma unroll
    for (int p = 0; p < 10; p++){
        float lo = bias[2*p];
        float hi = (2*p + 1 < C_) ? bias[2*p + 1] : 0.f;
        float2 t = make_float2(lo, hi);
        acc[p] = *reinterpret_cast<unsigned long long*>(&t);
    }

    // thread tid owns global row (row_base + tid): box = tid>>8, row-in-box = tid&255
    uint32_t box_off = (uint32_t)(tid >> 8) * BOX_BYTES;
    uint32_t rin = (uint32_t)(tid & 255);

    for (int s = 0; s < NSTAGE; s++){
        int buf = s & 1;
        uint32_t parity = (s >> 1) & 1;
        mbar_wait(mbar[buf], parity);

        const char* bsrc = smem_raw + (buf ? OFF_BUF1 : OFF_BUF0) + box_off;
#pragma unroll
        for (int q = 0; q < KCHUNK / 4; q++){
            uint32_t off = rin * 128 + q * 16;
            uint32_t sw = off ^ ((off >> 3) & 0x70);
            float4 a = *reinterpret_cast<const float4*>(bsrc + sw);
#pragma unroll
            for (int j = 0; j < 4; j++){
                unsigned long long xa = pack2((&a.x)[j]);
                int d = s * KCHUNK + q * 4 + j;
#pragma unroll
                for (int pp = 0; pp < 5; pp++){
                    ulonglong2 wv =
                        *reinterpret_cast<const ulonglong2*>(&w2[d * 10 + pp * 2]);
                    acc[2*pp]   = fma2(xa, wv.x, acc[2*pp]);
                    acc[2*pp+1] = fma2(xa, wv.y, acc[2*pp+1]);
                }
            }
        }

        if (s + 2 < NSTAGE){
            __syncthreads();   // all threads done reading buf
            if (tid == 0){
                mbar_expect_tx(mbar[buf], STAGE_BYTES);
                tma_load_2d(buf_u32[buf],             &tmap,
                            (s + 2) * KCHUNK, row_base,       mbar[buf]);
                tma_load_2d(buf_u32[buf] + BOX_BYTES, &tmap,
                            (s + 2) * KCHUNK, row_base + 256, mbar[buf]);
            }
        }
    }

    size_t row = (size_t)row_base + tid;
    unsigned long long* o = reinterpret_cast<unsigned long long*>(g_emis + row * CP);
#pragma unroll
    for (int p = 0; p < 10; p++) o[p] = acc[p];
}

// ---------------------------------------------------------------------------
// Kernel B1: Viterbi forward (exact R5 version). 256 blocks x 32 threads,
// one warp per batch. SHFL gather, fma-form mask blend (bit-exact for
// m in {0,1}), history streamed to gmem for the bp kernel.
// ---------------------------------------------------------------------------
__global__ void __launch_bounds__(32) fwd_kernel(const float* __restrict__ masks,
                                                 const float* __restrict__ trans){
    __shared__ float m_sh[L_];
    int lane = threadIdx.x & 31;
    int b = blockIdx.x;
    bool active = lane < C_;
    int c = active ? lane : 0;

    float Trow[C_];
#pragma unroll
    for (int j = 0; j < C_; j++) Trow[j] = trans[c * C_ + j];

    const float* eb = g_emis + (size_t)b * L_ * CP;
    const float* mb = masks + (size_t)b * L_;
    float* ghb = g_hist + (size_t)b * (L_ + 1) * CP;

    for (int i = lane; i < L_; i += 32) m_sh[i] = mb[i];
    __syncwarp();

    float s = (lane == C_ - 2) ? 0.f : -10000.f;   // start_idx = C-2
    if (active) ghb[lane] = s;

    int ld_lane = active ? lane : 0;
    float e0 = eb[0 * CP + ld_lane];
    float e1 = eb[1 * CP + ld_lane];
    float e2 = eb[2 * CP + ld_lane];
    float e3 = eb[3 * CP + ld_lane];

#define VSTEP(T, EREG)                                                         \
    {                                                                          \
        float m = m_sh[T];                                                     \
        float om = 1.0f - m;                                                   \
        float inner = fmaf((EREG), m, s * om);   /* off critical path */       \
        float v[C_];                                                           \
        _Pragma("unroll")                                                      \
        for (int j = 0; j < C_; j++)                                           \
            v[j] = __shfl_sync(0xffffffffu, s, j) + Trow[j];                   \
        _Pragma("unroll")                                                      \
        for (int stp = 1; stp < C_; stp <<= 1){                                \
            _Pragma("unroll")                                                  \
            for (int j = 0; j + stp < C_; j += (stp << 1))                     \
                v[j] = fmaxf(v[j], v[j + stp]);                                \
        }                                                                      \
        s = fmaf(v[0], m, inner);                                              \
        if (active) ghb[((T) + 1) * CP + lane] = s;                            \
    }

    for (int t = 0; t < L_; t += 4){
        VSTEP(t, e0);     e0 = (t + 4 < L_) ? eb[(t + 4) * CP + ld_lane] : 0.f;
        VSTEP(t + 1, e1); e1 = (t + 5 < L_) ? eb[(t + 5) * CP + ld_lane] : 0.f;
        VSTEP(t + 2, e2); e2 = (t + 6 < L_) ? eb[(t + 6) * CP + ld_lane] : 0.f;
        VSTEP(t + 3, e3); e3 = (t + 7 < L_) ? eb[(t + 7) * CP + ld_lane] : 0.f;
    }
#undef VSTEP
}

// ---------------------------------------------------------------------------
// Kernel B2: backpointers + backtrace (unchanged).
// ---------------------------------------------------------------------------
__global__ void __launch_bounds__(512) bp_kernel(const float* __restrict__ masks,
                                                 const float* __restrict__ trans,
                                                 float* __restrict__ out){
    __shared__ float T_sh[C_][CP];
    __shared__ float m2[L_];
    __shared__ signed char bp_sh[L_][CP];   // col 19 reused for tags
    int tid = threadIdx.x;
    int b = blockIdx.x;

    for (int i = tid; i < C_ * CP; i += 512){
        int cc = i / CP, j = i % CP;
        T_sh[cc][j] = (j < C_) ? trans[cc * C_ + j] : 0.f;
    }
    if (tid < L_) m2[tid] = masks[(size_t)b * L_ + tid];
    __syncthreads();

    {
        int t = tid;   // 0..511
        const float* h = g_hist + ((size_t)b * (L_ + 1) + t) * CP;
        float4 h0 = *reinterpret_cast<const float4*>(h + 0);
        float4 h1 = *reinterpret_cast<const float4*>(h + 4);
        float4 h2 = *reinterpret_cast<const float4*>(h + 8);
        float4 h3 = *reinterpret_cast<const float4*>(h + 12);
        float4 h4 = *reinterpret_cast<const float4*>(h + 16);
        float hv[C_];
        hv[0]=h0.x; hv[1]=h0.y; hv[2]=h0.z; hv[3]=h0.w;
        hv[4]=h1.x; hv[5]=h1.y; hv[6]=h1.z; hv[7]=h1.w;
        hv[8]=h2.x; hv[9]=h2.y; hv[10]=h2.z; hv[11]=h2.w;
        hv[12]=h3.x; hv[13]=h3.y; hv[14]=h3.z; hv[15]=h3.w;
        hv[16]=h4.x; hv[17]=h4.y; hv[18]=h4.z;

#pragma unroll
        for (int cc = 0; cc < C_; cc++){
            const float* tr = &T_sh[cc][0];
            float best = hv[0] + tr[0];
            int idx = 0;
#pragma unroll
            for (int j = 1; j < C_; j++){
                float val = hv[j] + tr[j];
                bool gt = val > best;          // strict > : leftmost wins ties
                best = gt ? val : best;
                idx  = gt ? j : idx;
            }
            bp_sh[t][cc] = (signed char)idx;
        }
    }

    // final score + start tag (warp 0)
    float fv = -3.4e38f; int fi = 999;
    if (tid < 32){
        int lane = tid;
        bool active = lane < C_;
        if (active)
            fv = g_hist[((size_t)b * (L_ + 1) + L_) * CP + lane]
               + trans[(C_ - 1) * C_ + lane];
        if (active) fi = lane;
#pragma unroll
        for (int off = 16; off > 0; off >>= 1){
            float ov = __shfl_down_sync(0xffffffffu, fv, off);
            int oi = __shfl_down_sync(0xffffffffu, fi, off);
            if (ov > fv || (ov == fv && oi < fi)){ fv = ov; fi = oi; }
        }
    }
    __syncthreads();

    if (tid == 0){
        out[b] = fv;
        int cur = fi;
        for (int t = L_ - 1; t >= 0; t--){
            bool valid = m2[t] > 0.f;
            bp_sh[t][C_] = valid ? (signed char)cur : (signed char)(-1);
            if (valid) cur = bp_sh[t][cur];
        }
    }
    __syncthreads();

    float* po = out + B_ + (size_t)b * L_;
    po[tid] = (float)bp_sh[tid][C_];
}

// ---------------------------------------------------------------------------
typedef CUresult (*PFN_encodeTiled)(CUtensorMap*, CUtensorMapDataType, cuuint32_t,
                                    void*, const cuuint64_t*, const cuuint64_t*,
                                    const cuuint32_t*, const cuuint32_t*,
                                    CUtensorMapInterleave, CUtensorMapSwizzle,
                                    CUtensorMapL2promotion, CUtensorMapFloatOOBfill);

extern "C" void kernel_launch(void* const* d_in, const int* in_sizes, int n_in,
                              void* d_out, int out_size){
    const float* feats = (const float*)d_in[0];
    const float* masks = (const float*)d_in[1];
    const float* W     = (const float*)d_in[2];
    const float* bias  = (const float*)d_in[3];
    const float* trans = (const float*)d_in[4];
    float* out = (float*)d_out;

    // Encode TMA descriptor (host struct fill — no allocation, deterministic).
    PFN_encodeTiled encode = nullptr;
#if CUDART_VERSION >= 12050
    {
        cudaDriverEntryPointQueryResult qr;
        cudaGetDriverEntryPointByVersion("cuTensorMapEncodeTiled",
                                         (void**)&encode, 12000,
                                         cudaEnableDefault, &qr);
    }
#else
    {
        cudaDriverEntryPointQueryResult qr;
        cudaGetDriverEntryPoint("cuTensorMapEncodeTiled", (void**)&encode,
                                cudaEnableDefault, &qr);
    }
#endif
    static CUtensorMap tmap;
    {
        cuuint64_t dims[2]    = { (cuuint64_t)D_, (cuuint64_t)BL };
        cuuint64_t strides[1] = { (cuuint64_t)D_ * sizeof(float) };
        cuuint32_t box[2]     = { (cuuint32_t)KCHUNK, 256u };
        cuuint32_t estr[2]    = { 1u, 1u };
        encode(&tmap, CU_TENSOR_MAP_DATA_TYPE_FLOAT32, 2, (void*)feats,
               dims, strides, box, estr,
               CU_TENSOR_MAP_INTERLEAVE_NONE, CU_TENSOR_MAP_SWIZZLE_128B,
               CU_TENSOR_MAP_L2_PROMOTION_L2_128B,
               CU_TENSOR_MAP_FLOAT_OOB_FILL_NONE);
    }

    cudaFuncSetAttribute(emis_kernel, cudaFuncAttributeMaxDynamicSharedMemorySize, SMEM_TOT);
    emis_kernel<<<BL / ROWS_BLK, 512, SMEM_TOT>>>(tmap, W, bias);
    fwd_kernel<<<B_, 32>>>(masks, trans);
    bp_kernel<<<B_, 512>>>(masks, trans, out);
}

// round 15
// speedup vs baseline: 1.3340x; 1.3340x over previous
#include <cuda_runtime.h>
#include <cuda.h>
#include <cstdint>
#include <cstddef>

#define B_ 256
#define L_ 512
#define D_ 768
#define C_ 19
#define CP 20
#define BL (B_*L_)

// emis staging geometry (TMA, SW64): 1024 rows/block, 64B per row per stage
#define KCHUNK 16                           // floats per stage per row (64B)
#define NSTAGE (D_ / KCHUNK)                // 48
#define ROWS_BLK 1024
#define BOX_ROWS 256
#define BOX_BYTES (BOX_ROWS * 64)           // 16384 (one UTMALDG)
#define STAGE_BYTES (4 * BOX_BYTES)         // 65536 per stage buffer (1024 rows)
#define W_BYTES (D_ * 10 * 8)               // 61440 (multiple of 1024)
#define OFF_BUF0 W_BYTES                    // 61440
#define OFF_BUF1 (W_BYTES + STAGE_BYTES)    // 126976
#define OFF_MBAR (W_BYTES + 2 * STAGE_BYTES)// 192512
#define SMEM_TOT (OFF_MBAR + 16)            // 192528

// Emission scratch, padded to 20 floats/row
__device__ float g_emis[(size_t)BL * CP];
// Score history: rows 0..512 per batch
__device__ float g_hist[(size_t)B_ * (L_ + 1) * CP];

__device__ __forceinline__ unsigned long long pack2(float x){
    unsigned long long r;
    asm("mov.b64 %0, {%1, %1};" : "=l"(r) : "f"(x));
    return r;
}
__device__ __forceinline__ unsigned long long fma2(unsigned long long a,
                                                   unsigned long long b,
                                                   unsigned long long c){
    unsigned long long d;
    asm("fma.rn.f32x2 %0, %1, %2, %3;" : "=l"(d) : "l"(a), "l"(b), "l"(c));
    return d;
}
__device__ __forceinline__ uint32_t smem_u32(const void* p){
    uint32_t a;
    asm("{ .reg .u64 t; cvta.to.shared.u64 t, %1; cvt.u32.u64 %0, t; }"
        : "=r"(a) : "l"(p));
    return a;
}
__device__ __forceinline__ void mbar_init(uint32_t mbar, uint32_t cnt){
    asm volatile("mbarrier.init.shared.b64 [%0], %1;" :: "r"(mbar), "r"(cnt) : "memory");
}
__device__ __forceinline__ void mbar_expect_tx(uint32_t mbar, uint32_t bytes){
    asm volatile("mbarrier.arrive.expect_tx.shared.b64 _, [%0], %1;"
                 :: "r"(mbar), "r"(bytes) : "memory");
}
__device__ __forceinline__ void mbar_wait(uint32_t mbar, uint32_t parity){
    asm volatile(
        "{\n\t"
        ".reg .pred P;\n\t"
        "WAIT_%=:\n\t"
        "mbarrier.try_wait.parity.acquire.cta.shared::cta.b64 P, [%0], %1, 0x989680;\n\t"
        "@P bra DONE_%=;\n\t"
        "bra WAIT_%=;\n\t"
        "DONE_%=:\n\t"
        "}" :: "r"(mbar), "r"(parity) : "memory");
}
__device__ __forceinline__ void tma_load_2d(uint32_t smem_addr, const CUtensorMap* tmap,
                                            int cx, int cy, uint32_t mbar){
    asm volatile(
        "cp.async.bulk.tensor.2d.shared::cta.global.tile.mbarrier::complete_tx::bytes "
        "[%0], [%1, {%2, %3}], [%4];"
        :: "r"(smem_addr), "l"(tmap), "r"(cx), "r"(cy), "r"(mbar) : "memory");
}

// ---------------------------------------------------------------------------
// Kernel A: emissions, TMA + SW64 staging. 128 blocks x 512 threads, 1024
// rows/block, 2 rows/thread. R14 showed R=1 makes LSU the binder (weight
// loads not amortized); R13 showed 8 warps leaves FMA 45% stalled. This
// config keeps R=2 LSU:FMA ratio (1792 < 2560 cyc/SM/stage) at 16 warps/SM
// AND runs a single full wave (grid 128 <= 148 SMs). FMA floor ~65us.
// ---------------------------------------------------------------------------
__global__ void __launch_bounds__(512) emis_kernel(const __grid_constant__ CUtensorMap tmap,
                                                   const float* __restrict__ W,
                                                   const float* __restrict__ bias){
    extern __shared__ char smem_raw[];
    unsigned long long* w2 = reinterpret_cast<unsigned long long*>(smem_raw);
    uint32_t base_u32 = smem_u32(smem_raw);
    uint32_t buf_u32[2] = { base_u32 + OFF_BUF0, base_u32 + OFF_BUF1 };
    uint32_t mbar[2]    = { base_u32 + OFF_MBAR, base_u32 + OFF_MBAR + 8 };
    int tid = threadIdx.x;
    int row_base = blockIdx.x * ROWS_BLK;

    // stage weights: w2[d*10 + p] = (W[2p][d], W[2p+1][d])
    for (int i = tid; i < D_ * 10; i += 512){
        int d = i / 10, p = i % 10;
        float lo = W[(2*p) * D_ + d];
        float hi = (2*p + 1 < C_) ? W[(2*p + 1) * D_ + d] : 0.f;
        float2 t = make_float2(lo, hi);
        w2[i] = *reinterpret_cast<unsigned long long*>(&t);
    }
    if (tid == 0){ mbar_init(mbar[0], 1); mbar_init(mbar[1], 1); }
    __syncthreads();

#define ISSUE_STAGE(S, BUF)                                                    \
    {                                                                          \
        mbar_expect_tx(mbar[BUF], STAGE_BYTES);                                \
        _Pragma("unroll")                                                      \
        for (int bx = 0; bx < 4; bx++)                                         \
            tma_load_2d(buf_u32[BUF] + bx * BOX_BYTES, &tmap,                  \
                        (S) * KCHUNK, row_base + bx * BOX_ROWS, mbar[BUF]);    \
    }

    if (tid == 0){ ISSUE_STAGE(0, 0); ISSUE_STAGE(1, 1); }

    unsigned long long accA[10], accB[10];
#pragma unroll
    for (int p = 0; p < 10; p++){
        float lo = bias[2*p];
        float hi = (2*p + 1 < C_) ? bias[2*p + 1] : 0.f;
        float2 t = make_float2(lo, hi);
        accA[p] = *reinterpret_cast<unsigned long long*>(&t);
        accB[p] = accA[p];
    }

    // thread tid owns rows tid and tid+512 within the block tile
    int rA = tid, rB = tid + 512;
    uint32_t boxA = (uint32_t)(rA >> 8) * BOX_BYTES, rinA = (uint32_t)(rA & 255);
    uint32_t boxB = (uint32_t)(rB >> 8) * BOX_BYTES, rinB = (uint32_t)(rB & 255);

    for (int s = 0; s < NSTAGE; s++){
        int buf = s & 1;
        uint32_t parity = (s >> 1) & 1;
        mbar_wait(mbar[buf], parity);

        const char* bsrc = smem_raw + (buf ? OFF_BUF1 : OFF_BUF0);
        const char* pa = bsrc + boxA;
        const char* pb = bsrc + boxB;
#pragma unroll
        for (int q = 0; q < KCHUNK / 4; q++){
            uint32_t offA = rinA * 64 + q * 16;
            uint32_t offB = rinB * 64 + q * 16;
            float4 a = *reinterpret_cast<const float4*>(
                pa + (offA ^ ((offA >> 3) & 0x30)));
            float4 b = *reinterpret_cast<const float4*>(
                pb + (offB ^ ((offB >> 3) & 0x30)));
#pragma unroll
            for (int j = 0; j < 4; j++){
                unsigned long long xa = pack2((&a.x)[j]);
                unsigned long long xb = pack2((&b.x)[j]);
                int d = s * KCHUNK + q * 4 + j;
#pragma unroll
                for (int pp = 0; pp < 5; pp++){
                    ulonglong2 wv =
                        *reinterpret_cast<const ulonglong2*>(&w2[d * 10 + pp * 2]);
                    accA[2*pp]   = fma2(xa, wv.x, accA[2*pp]);
                    accA[2*pp+1] = fma2(xa, wv.y, accA[2*pp+1]);
                    accB[2*pp]   = fma2(xb, wv.x, accB[2*pp]);
                    accB[2*pp+1] = fma2(xb, wv.y, accB[2*pp+1]);
                }
            }
        }

        if (s + 2 < NSTAGE){
            __syncthreads();   // all threads done reading buf
            if (tid == 0){ ISSUE_STAGE(s + 2, buf); }
        }
    }
#undef ISSUE_STAGE

    size_t rowA = (size_t)row_base + rA;
    size_t rowB = (size_t)row_base + rB;
    unsigned long long* oA = reinterpret_cast<unsigned long long*>(g_emis + rowA * CP);
    unsigned long long* oB = reinterpret_cast<unsigned long long*>(g_emis + rowB * CP);
#pragma unroll
    for (int p = 0; p < 10; p++){ oA[p] = accA[p]; oB[p] = accB[p]; }
}

// ---------------------------------------------------------------------------
// Kernel B1: Viterbi forward (exact R5 version). 256 blocks x 32 threads,
// one warp per batch. SHFL gather, fma-form mask blend (bit-exact for
// m in {0,1}), history streamed to gmem for the bp kernel.
// ---------------------------------------------------------------------------
__global__ void __launch_bounds__(32) fwd_kernel(const float* __restrict__ masks,
                                                 const float* __restrict__ trans){
    __shared__ float m_sh[L_];
    int lane = threadIdx.x & 31;
    int b = blockIdx.x;
    bool active = lane < C_;
    int c = active ? lane : 0;

    float Trow[C_];
#pragma unroll
    for (int j = 0; j < C_; j++) Trow[j] = trans[c * C_ + j];

    const float* eb = g_emis + (size_t)b * L_ * CP;
    const float* mb = masks + (size_t)b * L_;
    float* ghb = g_hist + (size_t)b * (L_ + 1) * CP;

    for (int i = lane; i < L_; i += 32) m_sh[i] = mb[i];
    __syncwarp();

    float s = (lane == C_ - 2) ? 0.f : -10000.f;   // start_idx = C-2
    if (active) ghb[lane] = s;

    int ld_lane = active ? lane : 0;
    float e0 = eb[0 * CP + ld_lane];
    float e1 = eb[1 * CP + ld_lane];
    float e2 = eb[2 * CP + ld_lane];
    float e3 = eb[3 * CP + ld_lane];

#define VSTEP(T, EREG)                                                         \
    {                                                                          \
        float m = m_sh[T];                                                     \
        float om = 1.0f - m;                                                   \
        float inner = fmaf((EREG), m, s * om);   /* off critical path */       \
        float v[C_];                                                           \
        _Pragma("unroll")                                                      \
        for (int j = 0; j < C_; j++)                                           \
            v[j] = __shfl_sync(0xffffffffu, s, j) + Trow[j];                   \
        _Pragma("unroll")                                                      \
        for (int stp = 1; stp < C_; stp <<= 1){                                \
            _Pragma("unroll")                                                  \
            for (int j = 0; j + stp < C_; j += (stp << 1))                     \
                v[j] = fmaxf(v[j], v[j + stp]);                                \
        }                                                                      \
        s = fmaf(v[0], m, inner);                                              \
        if (active) ghb[((T) + 1) * CP + lane] = s;                            \
    }

    for (int t = 0; t < L_; t += 4){
        VSTEP(t, e0);     e0 = (t + 4 < L_) ? eb[(t + 4) * CP + ld_lane] : 0.f;
        VSTEP(t + 1, e1); e1 = (t + 5 < L_) ? eb[(t + 5) * CP + ld_lane] : 0.f;
        VSTEP(t + 2, e2); e2 = (t + 6 < L_) ? eb[(t + 6) * CP + ld_lane] : 0.f;
        VSTEP(t + 3, e3); e3 = (t + 7 < L_) ? eb[(t + 7) * CP + ld_lane] : 0.f;
    }
#undef VSTEP
}

// ---------------------------------------------------------------------------
// Kernel B2: backpointers + backtrace (unchanged).
// ---------------------------------------------------------------------------
__global__ void __launch_bounds__(512) bp_kernel(const float* __restrict__ masks,
                                                 const float* __restrict__ trans,
                                                 float* __restrict__ out){
    __shared__ float T_sh[C_][CP];
    __shared__ float m2[L_];
    __shared__ signed char bp_sh[L_][CP];   // col 19 reused for tags
    int tid = threadIdx.x;
    int b = blockIdx.x;

    for (int i = tid; i < C_ * CP; i += 512){
        int cc = i / CP, j = i % CP;
        T_sh[cc][j] = (j < C_) ? trans[cc * C_ + j] : 0.f;
    }
    if (tid < L_) m2[tid] = masks[(size_t)b * L_ + tid];
    __syncthreads();

    {
        int t = tid;   // 0..511
        const float* h = g_hist + ((size_t)b * (L_ + 1) + t) * CP;
        float4 h0 = *reinterpret_cast<const float4*>(h + 0);
        float4 h1 = *reinterpret_cast<const float4*>(h + 4);
        float4 h2 = *reinterpret_cast<const float4*>(h + 8);
        float4 h3 = *reinterpret_cast<const float4*>(h + 12);
        float4 h4 = *reinterpret_cast<const float4*>(h + 16);
        float hv[C_];
        hv[0]=h0.x; hv[1]=h0.y; hv[2]=h0.z; hv[3]=h0.w;
        hv[4]=h1.x; hv[5]=h1.y; hv[6]=h1.z; hv[7]=h1.w;
        hv[8]=h2.x; hv[9]=h2.y; hv[10]=h2.z; hv[11]=h2.w;
        hv[12]=h3.x; hv[13]=h3.y; hv[14]=h3.z; hv[15]=h3.w;
        hv[16]=h4.x; hv[17]=h4.y; hv[18]=h4.z;

#pragma unroll
        for (int cc = 0; cc < C_; cc++){
            const float* tr = &T_sh[cc][0];
            float best = hv[0] + tr[0];
            int idx = 0;
#pragma unroll
            for (int j = 1; j < C_; j++){
                float val = hv[j] + tr[j];
                bool gt = val > best;          // strict > : leftmost wins ties
                best = gt ? val : best;
                idx  = gt ? j : idx;
            }
            bp_sh[t][cc] = (signed char)idx;
        }
    }

    // final score + start tag (warp 0)
    float fv = -3.4e38f; int fi = 999;
    if (tid < 32){
        int lane = tid;
        bool active = lane < C_;
        if (active)
            fv = g_hist[((size_t)b * (L_ + 1) + L_) * CP + lane]
               + trans[(C_ - 1) * C_ + lane];
        if (active) fi = lane;
#pragma unroll
        for (int off = 16; off > 0; off >>= 1){
            float ov = __shfl_down_sync(0xffffffffu, fv, off);
            int oi = __shfl_down_sync(0xffffffffu, fi, off);
            if (ov > fv || (ov == fv && oi < fi)){ fv = ov; fi = oi; }
        }
    }
    __syncthreads();

    if (tid == 0){
        out[b] = fv;
        int cur = fi;
        for (int t = L_ - 1; t >= 0; t--){
            bool valid = m2[t] > 0.f;
            bp_sh[t][C_] = valid ? (signed char)cur : (signed char)(-1);
            if (valid) cur = bp_sh[t][cur];
        }
    }
    __syncthreads();

    float* po = out + B_ + (size_t)b * L_;
    po[tid] = (float)bp_sh[tid][C_];
}

// ---------------------------------------------------------------------------
typedef CUresult (*PFN_encodeTiled)(CUtensorMap*, CUtensorMapDataType, cuuint32_t,
                                    void*, const cuuint64_t*, const cuuint64_t*,
                                    const cuuint32_t*, const cuuint32_t*,
                                    CUtensorMapInterleave, CUtensorMapSwizzle,
                                    CUtensorMapL2promotion, CUtensorMapFloatOOBfill);

extern "C" void kernel_launch(void* const* d_in, const int* in_sizes, int n_in,
                              void* d_out, int out_size){
    const float* feats = (const float*)d_in[0];
    const float* masks = (const float*)d_in[1];
    const float* W     = (const float*)d_in[2];
    const float* bias  = (const float*)d_in[3];
    const float* trans = (const float*)d_in[4];
    float* out = (float*)d_out;

    // Encode TMA descriptor (host struct fill — no allocation, deterministic).
    PFN_encodeTiled encode = nullptr;
#if CUDART_VERSION >= 12050
    {
        cudaDriverEntryPointQueryResult qr;
        cudaGetDriverEntryPointByVersion("cuTensorMapEncodeTiled",
                                         (void**)&encode, 12000,
                                         cudaEnableDefault, &qr);
    }
#else
    {
        cudaDriverEntryPointQueryResult qr;
        cudaGetDriverEntryPoint("cuTensorMapEncodeTiled", (void**)&encode,
                                cudaEnableDefault, &qr);
    }
#endif
    static CUtensorMap tmap;
    {
        cuuint64_t dims[2]    = { (cuuint64_t)D_, (cuuint64_t)BL };
        cuuint64_t strides[1] = { (cuuint64_t)D_ * sizeof(float) };
        cuuint32_t box[2]     = { (cuuint32_t)KCHUNK, (cuuint32_t)BOX_ROWS };
        cuuint32_t estr[2]    = { 1u, 1u };
        encode(&tmap, CU_TENSOR_MAP_DATA_TYPE_FLOAT32, 2, (void*)feats,
               dims, strides, box, estr,
               CU_TENSOR_MAP_INTERLEAVE_NONE, CU_TENSOR_MAP_SWIZZLE_64B,
               CU_TENSOR_MAP_L2_PROMOTION_L2_128B,
               CU_TENSOR_MAP_FLOAT_OOB_FILL_NONE);
    }

    cudaFuncSetAttribute(emis_kernel, cudaFuncAttributeMaxDynamicSharedMemorySize, SMEM_TOT);
    emis_kernel<<<BL / ROWS_BLK, 512, SMEM_TOT>>>(tmap, W, bias);
    fwd_kernel<<<B_, 32>>>(masks, trans);
    bp_kernel<<<B_, 512>>>(masks, trans, out);
}